// round 10
// baseline (speedup 1.0000x reference)
#include <cuda_runtime.h>

#define THETA 0.9999f

// IF-neuron spike rate over 50 steps, constant drive a, soft reset.
// Closed form floor(50*a/theta); exact f32 sim only near count boundaries.
__device__ __forceinline__ float rate50(float a) {
    if (a <= 0.0f) return 0.0f;
    if (a >= THETA) return 1.0f;
    float u = a * (50.0f / THETA);
    float k = floorf(u);
    float d = u - k;
    if (d > 1e-4f && d < 0.9999f) {
        return k * 0.02f;
    }
    float v = 0.0f, cnt = 0.0f;
    #pragma unroll
    for (int t = 0; t < 50; ++t) {
        v += a;
        if (v >= THETA) { v -= THETA; cnt += 1.0f; }
    }
    return cnt * 0.02f;
}

// Shared layout (floats):
//   A [0,184)      : mx (data at h+1, pads zero); A[0..64) reused as reduction scratch
//   B [184,3768)   : r1 (16 rows stride 184, data at h+1), then r3 (32 rows stride 112, data at h+1)
//   C [3768,9400)  : r2 (32 rows stride 176), then r4 (32 rows stride 88)
#define SM_TOTAL 9400
#define B_OFF 184
#define C_OFF 3768

__global__ __launch_bounds__(512, 2)
void catnet_kernel(const float* __restrict__ x,
                   const float* __restrict__ w1, const float* __restrict__ b1,
                   const float* __restrict__ w2, const float* __restrict__ b2,
                   const float* __restrict__ w3, const float* __restrict__ b3,
                   const float* __restrict__ wf, const float* __restrict__ bf,
                   float* __restrict__ out) {
    __shared__ float sm[SM_TOTAL];
    float* A = sm;
    float* B = sm + B_OFF;
    float* C = sm + C_OFF;
    const int tid = threadIdx.x;
    const int n = blockIdx.x;

    // zero all shared (establishes every pad cell)
    for (int i = tid; i < SM_TOTAL; i += 512) sm[i] = 0.0f;
    __syncthreads();

    // ---- stage 0: mean over time -> A[h+1] ----
    const float2* xn2 = (const float2*)(x + (long)n * (180 * 50));
    if (tid < 180) {
        const float2* xp = xn2 + tid * 25;
        float s0 = 0.0f, s1 = 0.0f;
        #pragma unroll
        for (int t = 0; t < 25; ++t) {
            float2 v = xp[t];
            s0 += v.x; s1 += v.y;
        }
        A[tid + 1] = (s0 + s1) / 50.0f;
    }
    __syncthreads();

    // ---- stage 1: conv (16,1,3) pad 1 + rate -> r1 in B (stride 184, data at h+1) ----
    for (int idx = tid; idx < 16 * 180; idx += 512) {
        int o = idx / 180, h = idx - o * 180;
        float a = b1[o]
                + A[h]     * w1[o * 3]
                + A[h + 1] * w1[o * 3 + 1]
                + A[h + 2] * w1[o * 3 + 2];
        B[o * 184 + h + 1] = rate50(a);
    }
    __syncthreads();

    // ---- stage 2: conv (32,16,9) pad 1 + rate -> r2 in C (stride 176) ----
    // 512 threads: o = tid/16 (32), 16 h-chunks of 11 (176 slots, 174 valid)
    {
        int o = tid >> 4;
        int h0 = (tid & 15) * 11;
        float acc[11];
        float bb = b2[o];
        #pragma unroll
        for (int j = 0; j < 11; ++j) acc[j] = bb;
        for (int c = 0; c < 16; ++c) {
            float win[19];
            const float* row = B + c * 184 + h0;
            #pragma unroll
            for (int j = 0; j < 19; ++j) win[j] = row[j];
            const float* wp = w2 + (o * 16 + c) * 9;
            #pragma unroll
            for (int k = 0; k < 9; ++k) {
                float wv = wp[k];
                #pragma unroll
                for (int j = 0; j < 11; ++j) acc[j] += win[j + k] * wv;
            }
        }
        #pragma unroll
        for (int j = 0; j < 11; ++j) {
            int h = h0 + j;
            if (h < 174) C[o * 176 + h] = rate50(acc[j]);
        }
    }
    __syncthreads();

    // ---- stage 3: sum-pool(2)*1.1 + rate -> r3 in B (stride 112, data at h+1) ----
    for (int idx = tid; idx < 32 * 87; idx += 512) {
        int o = idx / 87, h = idx - o * 87;
        float a = 1.1f * (C[o * 176 + 2 * h] + C[o * 176 + 2 * h + 1]);
        B[o * 112 + h + 1] = rate50(a);
    }
    // zero r3 pad cells (region previously held r1 data): idx 0 and 88..111 per row
    // (disjoint from stage-3 writes at 1..87, so same phase is race-free)
    if (tid < 32) {
        B[tid * 112] = 0.0f;
        #pragma unroll
        for (int j = 88; j < 112; ++j) B[tid * 112 + j] = 0.0f;
    }
    __syncthreads();

    // ---- stage 4: conv (32,32,7) pad 1 + rate -> r4 in C (stride 88) ----
    // 512 threads: o = tid/16 (32), 16 h-chunks of 6 (96 slots, 83 valid)
    {
        int o = tid >> 4;
        int h0 = (tid & 15) * 6;
        float acc[6];
        float bb = b3[o];
        #pragma unroll
        for (int j = 0; j < 6; ++j) acc[j] = bb;
        for (int c = 0; c < 32; ++c) {
            float win[12];
            const float* row = B + c * 112 + h0;
            #pragma unroll
            for (int j = 0; j < 12; ++j) win[j] = row[j];
            const float* wp = w3 + (o * 32 + c) * 7;
            #pragma unroll
            for (int k = 0; k < 7; ++k) {
                float wv = wp[k];
                #pragma unroll
                for (int j = 0; j < 6; ++j) acc[j] += win[j + k] * wv;
            }
        }
        #pragma unroll
        for (int j = 0; j < 6; ++j) {
            int h = h0 + j;
            if (h < 83) C[o * 88 + h] = rate50(acc[j]);
        }
    }
    __syncthreads();

    // ---- stage 5: dense out[n,o] = sum_{c,h} r4[c,h]*wf[o,c,h] + bf[o] ----
    {
        float p0 = 0.f, p1 = 0.f, p2 = 0.f, p3 = 0.f;
        for (int idx = tid; idx < 32 * 83; idx += 512) {
            int c = idx / 83, h = idx - c * 83;
            float v = C[c * 88 + h];
            int wi = c * 83 + h;
            p0 += v * wf[wi];
            p1 += v * wf[wi + 2656];
            p2 += v * wf[wi + 2 * 2656];
            p3 += v * wf[wi + 3 * 2656];
        }
        #pragma unroll
        for (int off = 16; off; off >>= 1) {
            p0 += __shfl_down_sync(0xffffffffu, p0, off);
            p1 += __shfl_down_sync(0xffffffffu, p1, off);
            p2 += __shfl_down_sync(0xffffffffu, p2, off);
            p3 += __shfl_down_sync(0xffffffffu, p3, off);
        }
        int lane = tid & 31, wid = tid >> 5;
        if (lane == 0) {
            A[wid * 4 + 0] = p0;
            A[wid * 4 + 1] = p1;
            A[wid * 4 + 2] = p2;
            A[wid * 4 + 3] = p3;
        }
    }
    __syncthreads();
    if (tid < 4) {
        float s = bf[tid];
        #pragma unroll
        for (int w = 0; w < 16; ++w) s += A[w * 4 + tid];
        out[n * 4 + tid] = s;
    }
}

extern "C" void kernel_launch(void* const* d_in, const int* in_sizes, int n_in,
                              void* d_out, int out_size) {
    const float* x  = (const float*)d_in[0];
    const float* w1 = (const float*)d_in[1];
    const float* b1 = (const float*)d_in[2];
    const float* w2 = (const float*)d_in[3];
    const float* b2 = (const float*)d_in[4];
    const float* w3 = (const float*)d_in[5];
    const float* b3 = (const float*)d_in[6];
    const float* wf = (const float*)d_in[7];
    const float* bf = (const float*)d_in[8];
    float* out = (float*)d_out;

    int n = in_sizes[0] / (180 * 50);   // batch size (256)
    catnet_kernel<<<n, 512>>>(x, w1, b1, w2, b2, w3, b3, wf, bf, out);
}

// round 11
// speedup vs baseline: 1.4583x; 1.4583x over previous
#include <cuda_runtime.h>

#define THETA 0.9999f

// IF-neuron spike rate over 50 steps, constant drive a, soft reset.
// Closed form floor(50*a/theta); exact f32 sim only near count boundaries.
__device__ __forceinline__ float rate50(float a) {
    if (a <= 0.0f) return 0.0f;
    if (a >= THETA) return 1.0f;
    float u = a * (50.0f / THETA);
    float k = floorf(u);
    float d = u - k;
    if (d > 1e-4f && d < 0.9999f) {
        return k * 0.02f;
    }
    float v = 0.0f, cnt = 0.0f;
    #pragma unroll
    for (int t = 0; t < 50; ++t) {
        v += a;
        if (v >= THETA) { v -= THETA; cnt += 1.0f; }
    }
    return cnt * 0.02f;
}

// Shared layout (floats):
//   A [0,184)    : mx (data at h+1, pads zero); later 32 warp-reduction partials
//   B [184,3256) : r1 (16 rows stride 184, data at h+1) then r3 (32 rows stride 96, data at h+1)
//   C [3256,8888): r2 (32 rows stride 176) then r4 (32 rows stride 88)
#define SM_TOTAL 8888
#define B_OFF 184
#define C_OFF 3256

__global__ __launch_bounds__(256, 2)
void catnet_kernel(const float* __restrict__ x,
                   const float* __restrict__ w1, const float* __restrict__ b1,
                   const float* __restrict__ w2, const float* __restrict__ b2,
                   const float* __restrict__ w3, const float* __restrict__ b3,
                   const float* __restrict__ wf, const float* __restrict__ bf,
                   float* __restrict__ out) {
    __shared__ float sm[SM_TOTAL];
    float* A = sm;
    float* B = sm + B_OFF;
    float* C = sm + C_OFF;
    const int tid = threadIdx.x;
    const int n = blockIdx.x;

    // zero all shared (covers all pad positions for mx and r1)
    for (int i = tid; i < SM_TOTAL; i += 256) sm[i] = 0.0f;
    __syncthreads();

    // ---- stage 0: mean over time: x[n,0,h,0,t] -> A[h+1] ----
    const float2* xn2 = (const float2*)(x + (long)n * (180 * 50));
    for (int h = tid; h < 180; h += 256) {
        const float2* xp = xn2 + h * 25;
        float s0 = 0.0f, s1 = 0.0f;
        #pragma unroll
        for (int t = 0; t < 25; ++t) {
            float2 v = xp[t];
            s0 += v.x; s1 += v.y;
        }
        A[h + 1] = (s0 + s1) / 50.0f;
    }
    __syncthreads();

    // ---- stage 1: conv (16,1,3) pad 1 + rate -> B (r1, stride 184) ----
    for (int idx = tid; idx < 16 * 180; idx += 256) {
        int o = idx / 180, h = idx - o * 180;
        float a = b1[o]
                + A[h]     * w1[o * 3]
                + A[h + 1] * w1[o * 3 + 1]
                + A[h + 2] * w1[o * 3 + 2];
        B[o * 184 + h + 1] = rate50(a);
    }
    __syncthreads();

    // ---- stage 2: conv (32,16,9) pad 1 + rate -> C (r2, stride 176) ----
    // thread -> (o = tid/8, h-block of 22). Channel loop manually unrolled x2:
    // both channels' windows + weights are issued before the FMA blocks, so
    // load latency is covered by twice the independent-load window.
    // Per-acc FMA order (c ascending, k ascending) identical to the rolled loop.
    {
        int o = tid >> 3;
        int h0 = (tid & 7) * 22;
        float acc[22];
        float bb = b2[o];
        #pragma unroll
        for (int j = 0; j < 22; ++j) acc[j] = bb;
        #pragma unroll 1
        for (int c = 0; c < 16; c += 2) {
            float win_a[30], win_b[30];
            const float* row_a = B + c * 184 + h0;
            const float* row_b = row_a + 184;
            #pragma unroll
            for (int j = 0; j < 30; ++j) win_a[j] = row_a[j];
            #pragma unroll
            for (int j = 0; j < 30; ++j) win_b[j] = row_b[j];
            const float* wpa = w2 + (o * 16 + c) * 9;
            float wa[9], wb[9];
            #pragma unroll
            for (int k = 0; k < 9; ++k) wa[k] = wpa[k];
            #pragma unroll
            for (int k = 0; k < 9; ++k) wb[k] = wpa[9 + k];
            #pragma unroll
            for (int k = 0; k < 9; ++k) {
                #pragma unroll
                for (int j = 0; j < 22; ++j) acc[j] += win_a[j + k] * wa[k];
            }
            #pragma unroll
            for (int k = 0; k < 9; ++k) {
                #pragma unroll
                for (int j = 0; j < 22; ++j) acc[j] += win_b[j + k] * wb[k];
            }
        }
        #pragma unroll
        for (int j = 0; j < 22; ++j) C[o * 176 + h0 + j] = rate50(acc[j]);
    }
    __syncthreads();

    // ---- stage 3: sum-pool(2)*1.1 + rate -> B (r3, stride 96, data at h+1) ----
    for (int idx = tid; idx < 32 * 87; idx += 256) {
        int o = idx / 87, h = idx - o * 87;
        float a = 1.1f * (C[o * 176 + 2 * h] + C[o * 176 + 2 * h + 1]);
        B[o * 96 + h + 1] = rate50(a);
    }
    // zero r3 pads (region B previously held r1 data) + zero reduction scratch
    if (tid < 32) {
        B[tid * 96] = 0.0f;
        #pragma unroll
        for (int j = 88; j < 96; ++j) B[tid * 96 + j] = 0.0f;
        A[tid] = 0.0f;
    }
    __syncthreads();

    // ---- stage 4: conv (32,32,7) pad 1 + rate -> C (r4, stride 88) ----
    // thread -> (o = tid/8, h-block of 11). Channel loop unrolled x2 as above.
    {
        int o = tid >> 3;
        int h0 = (tid & 7) * 11;
        float acc[11];
        float bb = b3[o];
        #pragma unroll
        for (int j = 0; j < 11; ++j) acc[j] = bb;
        #pragma unroll 1
        for (int c = 0; c < 32; c += 2) {
            float win_a[17], win_b[17];
            const float* row_a = B + c * 96 + h0;
            const float* row_b = row_a + 96;
            #pragma unroll
            for (int j = 0; j < 17; ++j) win_a[j] = row_a[j];
            #pragma unroll
            for (int j = 0; j < 17; ++j) win_b[j] = row_b[j];
            const float* wpa = w3 + (o * 32 + c) * 7;
            float wa[7], wb[7];
            #pragma unroll
            for (int k = 0; k < 7; ++k) wa[k] = wpa[k];
            #pragma unroll
            for (int k = 0; k < 7; ++k) wb[k] = wpa[7 + k];
            #pragma unroll
            for (int k = 0; k < 7; ++k) {
                #pragma unroll
                for (int j = 0; j < 11; ++j) acc[j] += win_a[j + k] * wa[k];
            }
            #pragma unroll
            for (int k = 0; k < 7; ++k) {
                #pragma unroll
                for (int j = 0; j < 11; ++j) acc[j] += win_b[j + k] * wb[k];
            }
        }
        #pragma unroll
        for (int j = 0; j < 11; ++j) C[o * 88 + h0 + j] = rate50(acc[j]);
    }
    __syncthreads();

    // ---- stage 5: dense out[n,o] = sum_{c,h} r4[c,h]*wf[o,c,h] + bf[o] ----
    {
        float p0 = 0.f, p1 = 0.f, p2 = 0.f, p3 = 0.f;
        for (int idx = tid; idx < 32 * 83; idx += 256) {
            int c = idx / 83, h = idx - c * 83;
            float v = C[c * 88 + h];
            int wi = c * 83 + h;
            p0 += v * wf[wi];
            p1 += v * wf[wi + 2656];
            p2 += v * wf[wi + 2 * 2656];
            p3 += v * wf[wi + 3 * 2656];
        }
        #pragma unroll
        for (int off = 16; off; off >>= 1) {
            p0 += __shfl_down_sync(0xffffffffu, p0, off);
            p1 += __shfl_down_sync(0xffffffffu, p1, off);
            p2 += __shfl_down_sync(0xffffffffu, p2, off);
            p3 += __shfl_down_sync(0xffffffffu, p3, off);
        }
        int lane = tid & 31, wid = tid >> 5;
        if (lane == 0) {
            A[wid * 4 + 0] = p0;
            A[wid * 4 + 1] = p1;
            A[wid * 4 + 2] = p2;
            A[wid * 4 + 3] = p3;
        }
    }
    __syncthreads();
    if (tid < 4) {
        float s = bf[tid];
        #pragma unroll
        for (int w = 0; w < 8; ++w) s += A[w * 4 + tid];
        out[n * 4 + tid] = s;
    }
}

extern "C" void kernel_launch(void* const* d_in, const int* in_sizes, int n_in,
                              void* d_out, int out_size) {
    const float* x  = (const float*)d_in[0];
    const float* w1 = (const float*)d_in[1];
    const float* b1 = (const float*)d_in[2];
    const float* w2 = (const float*)d_in[3];
    const float* b2 = (const float*)d_in[4];
    const float* w3 = (const float*)d_in[5];
    const float* b3 = (const float*)d_in[6];
    const float* wf = (const float*)d_in[7];
    const float* bf = (const float*)d_in[8];
    float* out = (float*)d_out;

    int n = in_sizes[0] / (180 * 50);   // batch size (256)
    catnet_kernel<<<n, 256>>>(x, w1, b1, w2, b2, w3, b3, wf, bf, out);
}

// round 12
// speedup vs baseline: 1.5101x; 1.0355x over previous
#include <cuda_runtime.h>

#define THETA 0.9999f

// IF-neuron spike rate over 50 steps, constant drive a, soft reset.
// Closed form floor(50*a/theta); exact f32 sim only near count boundaries.
__device__ __forceinline__ float rate50(float a) {
    if (a <= 0.0f) return 0.0f;
    if (a >= THETA) return 1.0f;
    float u = a * (50.0f / THETA);
    float k = floorf(u);
    float d = u - k;
    if (d > 1e-4f && d < 0.9999f) {
        return k * 0.02f;
    }
    float v = 0.0f, cnt = 0.0f;
    #pragma unroll
    for (int t = 0; t < 50; ++t) {
        v += a;
        if (v >= THETA) { v -= THETA; cnt += 1.0f; }
    }
    return cnt * 0.02f;
}

// Shared layout (floats). Strides chosen so conv window LDS are bank-conflict-free:
//   stage2: r1 stride 184 (=24 mod 32) with h-chunk 23  -> 32 distinct banks/load
//   stage4: r3 stride 120 (=24 mod 32) with h-chunk 11  -> 32 distinct banks/load
//   A [0,184)    : mx (data at h+1, pads zero); later 32 warp-reduction partials
//   B [184,4024) : r1 (16 rows stride 184, data at h+1) then r3 (32 rows stride 120, data at h+1)
//   C [4024,9656): r2 (32 rows stride 176) then r4 (32 rows stride 88)
#define SM_TOTAL 9656
#define B_OFF 184
#define C_OFF 4024

__global__ __launch_bounds__(256, 2)
void catnet_kernel(const float* __restrict__ x,
                   const float* __restrict__ w1, const float* __restrict__ b1,
                   const float* __restrict__ w2, const float* __restrict__ b2,
                   const float* __restrict__ w3, const float* __restrict__ b3,
                   const float* __restrict__ wf, const float* __restrict__ bf,
                   float* __restrict__ out) {
    __shared__ float sm[SM_TOTAL];
    float* A = sm;
    float* B = sm + B_OFF;
    float* C = sm + C_OFF;
    const int tid = threadIdx.x;
    const int n = blockIdx.x;

    // zero all shared (establishes every pad cell; also makes chunk-tail
    // over-reads in stage 2 read finite zeros)
    for (int i = tid; i < SM_TOTAL; i += 256) sm[i] = 0.0f;
    __syncthreads();

    // ---- stage 0: mean over time: x[n,0,h,0,t] -> A[h+1] ----
    const float2* xn2 = (const float2*)(x + (long)n * (180 * 50));
    for (int h = tid; h < 180; h += 256) {
        const float2* xp = xn2 + h * 25;
        float s0 = 0.0f, s1 = 0.0f;
        #pragma unroll
        for (int t = 0; t < 25; ++t) {
            float2 v = xp[t];
            s0 += v.x; s1 += v.y;
        }
        A[h + 1] = (s0 + s1) / 50.0f;
    }
    __syncthreads();

    // ---- stage 1: conv (16,1,3) pad 1 + rate -> B (r1, stride 184, data at h+1) ----
    for (int idx = tid; idx < 16 * 180; idx += 256) {
        int o = idx / 180, h = idx - o * 180;
        float a = b1[o]
                + A[h]     * w1[o * 3]
                + A[h + 1] * w1[o * 3 + 1]
                + A[h + 2] * w1[o * 3 + 2];
        B[o * 184 + h + 1] = rate50(a);
    }
    __syncthreads();

    // ---- stage 2: conv (32,16,9) pad 1 + rate -> C (r2, stride 176) ----
    // thread -> (o = tid/8, h-chunk of 23). Window LDS conflict-free
    // (stride 184 = 24 mod 32, 23s spans a tiling set). Tail chunks read
    // zeroed smem and are store-guarded.
    {
        int o = tid >> 3;
        int h0 = (tid & 7) * 23;
        float acc[23];
        float bb = b2[o];
        #pragma unroll
        for (int j = 0; j < 23; ++j) acc[j] = bb;
        #pragma unroll 1
        for (int c = 0; c < 16; ++c) {
            float win[31];
            const float* row = B + c * 184 + h0;
            #pragma unroll
            for (int j = 0; j < 31; ++j) win[j] = row[j];
            const float* wp = w2 + (o * 16 + c) * 9;
            #pragma unroll
            for (int k = 0; k < 9; ++k) {
                float wv = wp[k];
                #pragma unroll
                for (int j = 0; j < 23; ++j) acc[j] += win[j + k] * wv;
            }
        }
        #pragma unroll
        for (int j = 0; j < 23; ++j) {
            int h = h0 + j;
            if (h < 176) C[o * 176 + h] = rate50(acc[j]);   // 174 valid, 2 never read
        }
    }
    __syncthreads();

    // ---- stage 3: sum-pool(2)*1.1 + rate -> B (r3, stride 120, data at h+1) ----
    for (int idx = tid; idx < 32 * 87; idx += 256) {
        int o = idx / 87, h = idx - o * 87;
        float a = 1.1f * (C[o * 176 + 2 * h] + C[o * 176 + 2 * h + 1]);
        B[o * 120 + h + 1] = rate50(a);
    }
    // zero r3 pad cells (region previously held r1 data): index 0 and [88,120)
    // per row — disjoint from the writes above, so same phase is race-free.
    // Also zero reduction scratch (mx dead).
    if (tid < 32) {
        B[tid * 120] = 0.0f;
        #pragma unroll
        for (int j = 88; j < 120; ++j) B[tid * 120 + j] = 0.0f;
        A[tid] = 0.0f;
    }
    __syncthreads();

    // ---- stage 4: conv (32,32,7) pad 1 + rate -> C (r4, stride 88) ----
    // thread -> (o = tid/8, h-chunk of 11). Window LDS conflict-free
    // (stride 120 = 24 mod 32, 11s spans a tiling set).
    {
        int o = tid >> 3;
        int h0 = (tid & 7) * 11;
        float acc[11];
        float bb = b3[o];
        #pragma unroll
        for (int j = 0; j < 11; ++j) acc[j] = bb;
        #pragma unroll 1
        for (int c = 0; c < 32; ++c) {
            float win[17];
            const float* row = B + c * 120 + h0;
            #pragma unroll
            for (int j = 0; j < 17; ++j) win[j] = row[j];
            const float* wp = w3 + (o * 32 + c) * 7;
            #pragma unroll
            for (int k = 0; k < 7; ++k) {
                float wv = wp[k];
                #pragma unroll
                for (int j = 0; j < 11; ++j) acc[j] += win[j + k] * wv;
            }
        }
        #pragma unroll
        for (int j = 0; j < 11; ++j) C[o * 88 + h0 + j] = rate50(acc[j]);  // 83 valid
    }
    __syncthreads();

    // ---- stage 5: dense out[n,o] = sum_{c,h} r4[c,h]*wf[o,c,h] + bf[o] ----
    {
        float p0 = 0.f, p1 = 0.f, p2 = 0.f, p3 = 0.f;
        for (int idx = tid; idx < 32 * 83; idx += 256) {
            int c = idx / 83, h = idx - c * 83;
            float v = C[c * 88 + h];
            int wi = c * 83 + h;
            p0 += v * wf[wi];
            p1 += v * wf[wi + 2656];
            p2 += v * wf[wi + 2 * 2656];
            p3 += v * wf[wi + 3 * 2656];
        }
        #pragma unroll
        for (int off = 16; off; off >>= 1) {
            p0 += __shfl_down_sync(0xffffffffu, p0, off);
            p1 += __shfl_down_sync(0xffffffffu, p1, off);
            p2 += __shfl_down_sync(0xffffffffu, p2, off);
            p3 += __shfl_down_sync(0xffffffffu, p3, off);
        }
        int lane = tid & 31, wid = tid >> 5;
        if (lane == 0) {
            A[wid * 4 + 0] = p0;
            A[wid * 4 + 1] = p1;
            A[wid * 4 + 2] = p2;
            A[wid * 4 + 3] = p3;
        }
    }
    __syncthreads();
    if (tid < 4) {
        float s = bf[tid];
        #pragma unroll
        for (int w = 0; w < 8; ++w) s += A[w * 4 + tid];
        out[n * 4 + tid] = s;
    }
}

extern "C" void kernel_launch(void* const* d_in, const int* in_sizes, int n_in,
                              void* d_out, int out_size) {
    const float* x  = (const float*)d_in[0];
    const float* w1 = (const float*)d_in[1];
    const float* b1 = (const float*)d_in[2];
    const float* w2 = (const float*)d_in[3];
    const float* b2 = (const float*)d_in[4];
    const float* w3 = (const float*)d_in[5];
    const float* b3 = (const float*)d_in[6];
    const float* wf = (const float*)d_in[7];
    const float* bf = (const float*)d_in[8];
    float* out = (float*)d_out;

    int n = in_sizes[0] / (180 * 50);   // batch size (256)
    catnet_kernel<<<n, 256>>>(x, w1, b1, w2, b2, w3, b3, wf, bf, out);
}

// round 14
// speedup vs baseline: 1.6227x; 1.0746x over previous
#include <cuda_runtime.h>

#define THETA 0.9999f

// IF-neuron spike rate over 50 steps, constant drive a, soft reset.
// Closed form floor(50*a/theta); exact f32 sim only near count boundaries.
__device__ __forceinline__ float rate50(float a) {
    if (a <= 0.0f) return 0.0f;
    if (a >= THETA) return 1.0f;
    float u = a * (50.0f / THETA);
    float k = floorf(u);
    float d = u - k;
    if (d > 1e-4f && d < 0.9999f) {
        return k * 0.02f;
    }
    float v = 0.0f, cnt = 0.0f;
    #pragma unroll
    for (int t = 0; t < 50; ++t) {
        v += a;
        if (v >= THETA) { v -= THETA; cnt += 1.0f; }
    }
    return cnt * 0.02f;
}

// Dynamic shared layout (floats):
//   A  [0,184)        : mx (data at h+1, pads zero); later warp-reduction partials
//   B  [184,4024)     : r1 (16 x stride 184, data at h+1) then r3 (32 x stride 120, data at h+1)
//   C  [4024,9656)    : r2 (32 x stride 176) then r4 (32 x stride 88)
//   W2 [9656,14296)   : w2 staged, 32 rows stride 145 (o*145 + c*9 + k)
//   W3 [14296,21496)  : w3 staged, 32 rows stride 225 (o*225 + c*7 + k)
// Conv window LDS conflict-free: stage2 stride 184 (24 mod 32) x chunk 23;
// stage4 stride 120 (24 mod 32) x chunk 11.
#define B_OFF   184
#define C_OFF   4024
#define W2_OFF  9656
#define W3_OFF  14296
#define SM_TOTAL 21496
#define SMEM_BYTES (SM_TOTAL * 4)

__global__ __launch_bounds__(256, 2)
void catnet_kernel(const float* __restrict__ x,
                   const float* __restrict__ w1, const float* __restrict__ b1,
                   const float* __restrict__ w2, const float* __restrict__ b2,
                   const float* __restrict__ w3, const float* __restrict__ b3,
                   const float* __restrict__ wf, const float* __restrict__ bf,
                   float* __restrict__ out) {
    extern __shared__ float sm[];
    float* A   = sm;
    float* B   = sm + B_OFF;
    float* C   = sm + C_OFF;
    float* W2s = sm + W2_OFF;
    float* W3s = sm + W3_OFF;
    const int tid = threadIdx.x;
    const int n = blockIdx.x;

    // Stage weights global->shared (issued first; latency overlapped with
    // stages 0-1, complete by the pre-stage-2 barrier).
    // w2: 32 output rows of 16*9=144 -> stride 145
    #pragma unroll 4
    for (int i = tid; i < 32 * 144; i += 256) {
        int o = i / 144;
        W2s[o * 145 + (i - o * 144)] = w2[i];
    }
    // w3: 32 output rows of 32*7=224 -> stride 225
    #pragma unroll 4
    for (int i = tid; i < 32 * 224; i += 256) {
        int o = i / 224;
        W3s[o * 225 + (i - o * 224)] = w3[i];
    }

    // zero working region (pad cells + finite values for chunk-tail over-reads)
    for (int i = tid; i < W2_OFF; i += 256) sm[i] = 0.0f;
    __syncthreads();

    // ---- stage 0: mean over time: x[n,0,h,0,t] -> A[h+1] ----
    const float2* xn2 = (const float2*)(x + (long)n * (180 * 50));
    for (int h = tid; h < 180; h += 256) {
        const float2* xp = xn2 + h * 25;
        float s0 = 0.0f, s1 = 0.0f;
        #pragma unroll
        for (int t = 0; t < 25; ++t) {
            float2 v = xp[t];
            s0 += v.x; s1 += v.y;
        }
        A[h + 1] = (s0 + s1) / 50.0f;
    }
    __syncthreads();

    // ---- stage 1: conv (16,1,3) pad 1 + rate -> B (r1, stride 184, data at h+1) ----
    for (int idx = tid; idx < 16 * 180; idx += 256) {
        int o = idx / 180, h = idx - o * 180;
        float a = b1[o]
                + A[h]     * w1[o * 3]
                + A[h + 1] * w1[o * 3 + 1]
                + A[h + 2] * w1[o * 3 + 2];
        B[o * 184 + h + 1] = rate50(a);
    }
    __syncthreads();   // also guarantees weight staging is complete

    // ---- stage 2: conv (32,16,9) pad 1 + rate -> C (r2, stride 176) ----
    // thread -> (o = tid/8, h-chunk of 23). Window + weight LDS conflict-free.
    {
        int o = tid >> 3;
        int h0 = (tid & 7) * 23;
        float acc[23];
        float bb = b2[o];
        #pragma unroll
        for (int j = 0; j < 23; ++j) acc[j] = bb;
        const float* wrow = W2s + o * 145;
        #pragma unroll 1
        for (int c = 0; c < 16; ++c) {
            float win[31];
            const float* row = B + c * 184 + h0;
            #pragma unroll
            for (int j = 0; j < 31; ++j) win[j] = row[j];
            const float* wp = wrow + c * 9;
            #pragma unroll
            for (int k = 0; k < 9; ++k) {
                float wv = wp[k];
                #pragma unroll
                for (int j = 0; j < 23; ++j) acc[j] += win[j + k] * wv;
            }
        }
        #pragma unroll
        for (int j = 0; j < 23; ++j) {
            int h = h0 + j;
            if (h < 176) C[o * 176 + h] = rate50(acc[j]);   // 174 valid, 2 never read
        }
    }
    __syncthreads();

    // ---- stage 3: sum-pool(2)*1.1 + rate -> B (r3, stride 120, data at h+1) ----
    for (int idx = tid; idx < 32 * 87; idx += 256) {
        int o = idx / 87, h = idx - o * 87;
        float a = 1.1f * (C[o * 176 + 2 * h] + C[o * 176 + 2 * h + 1]);
        B[o * 120 + h + 1] = rate50(a);
    }
    // zero r3 pad cells (region previously held r1 data): index 0 and [88,120)
    // per row — disjoint from the writes above, so same phase is race-free.
    // Also zero reduction scratch (mx dead).
    if (tid < 32) {
        B[tid * 120] = 0.0f;
        #pragma unroll
        for (int j = 88; j < 120; ++j) B[tid * 120 + j] = 0.0f;
        A[tid] = 0.0f;
    }
    __syncthreads();

    // ---- stage 4: conv (32,32,7) pad 1 + rate -> C (r4, stride 88) ----
    // thread -> (o = tid/8, h-chunk of 11). Window + weight LDS conflict-free.
    {
        int o = tid >> 3;
        int h0 = (tid & 7) * 11;
        float acc[11];
        float bb = b3[o];
        #pragma unroll
        for (int j = 0; j < 11; ++j) acc[j] = bb;
        const float* wrow = W3s + o * 225;
        #pragma unroll 1
        for (int c = 0; c < 32; ++c) {
            float win[17];
            const float* row = B + c * 120 + h0;
            #pragma unroll
            for (int j = 0; j < 17; ++j) win[j] = row[j];
            const float* wp = wrow + c * 7;
            #pragma unroll
            for (int k = 0; k < 7; ++k) {
                float wv = wp[k];
                #pragma unroll
                for (int j = 0; j < 11; ++j) acc[j] += win[j + k] * wv;
            }
        }
        #pragma unroll
        for (int j = 0; j < 11; ++j) C[o * 88 + h0 + j] = rate50(acc[j]);  // 83 valid
    }
    __syncthreads();

    // ---- stage 5: dense out[n,o] = sum_{c,h} r4[c,h]*wf[o,c,h] + bf[o] ----
    {
        float p0 = 0.f, p1 = 0.f, p2 = 0.f, p3 = 0.f;
        for (int idx = tid; idx < 32 * 83; idx += 256) {
            int c = idx / 83, h = idx - c * 83;
            float v = C[c * 88 + h];
            int wi = c * 83 + h;
            p0 += v * wf[wi];
            p1 += v * wf[wi + 2656];
            p2 += v * wf[wi + 2 * 2656];
            p3 += v * wf[wi + 3 * 2656];
        }
        #pragma unroll
        for (int off = 16; off; off >>= 1) {
            p0 += __shfl_down_sync(0xffffffffu, p0, off);
            p1 += __shfl_down_sync(0xffffffffu, p1, off);
            p2 += __shfl_down_sync(0xffffffffu, p2, off);
            p3 += __shfl_down_sync(0xffffffffu, p3, off);
        }
        int lane = tid & 31, wid = tid >> 5;
        if (lane == 0) {
            A[wid * 4 + 0] = p0;
            A[wid * 4 + 1] = p1;
            A[wid * 4 + 2] = p2;
            A[wid * 4 + 3] = p3;
        }
    }
    __syncthreads();
    if (tid < 4) {
        float s = bf[tid];
        #pragma unroll
        for (int w = 0; w < 8; ++w) s += A[w * 4 + tid];
        out[n * 4 + tid] = s;
    }
}

extern "C" void kernel_launch(void* const* d_in, const int* in_sizes, int n_in,
                              void* d_out, int out_size) {
    const float* x  = (const float*)d_in[0];
    const float* w1 = (const float*)d_in[1];
    const float* b1 = (const float*)d_in[2];
    const float* w2 = (const float*)d_in[3];
    const float* b2 = (const float*)d_in[4];
    const float* w3 = (const float*)d_in[5];
    const float* b3 = (const float*)d_in[6];
    const float* wf = (const float*)d_in[7];
    const float* bf = (const float*)d_in[8];
    float* out = (float*)d_out;

    cudaFuncSetAttribute(catnet_kernel,
                         cudaFuncAttributeMaxDynamicSharedMemorySize, SMEM_BYTES);

    int n = in_sizes[0] / (180 * 50);   // batch size (256)
    catnet_kernel<<<n, 256, SMEM_BYTES>>>(x, w1, b1, w2, b2, w3, b3, wf, bf, out);
}